// round 10
// baseline (speedup 1.0000x reference)
#include <cuda_runtime.h>
#include <cuda_fp16.h>

// Problem constants (fixed by the dataset)
#define MAXN 100352
#define MAXE 1605632
#define H 64

// ---------------- device scratch (no allocations allowed) ----------------
__device__ __half g_hp16[MAXN * H]; // pre-scaled features  h' = dinv * h  (fp16)
__device__ float  g_a  [MAXN * H];  // aggregated features (gather output, fp32)
__device__ int    g_deg   [MAXN];
__device__ float  g_dinv  [MAXN];
__device__ int    g_rowptr[MAXN + 1];
__device__ int    g_cursor[MAXN];
__device__ int    g_csr   [MAXE];   // src index per CSR slot (grouped by dst)
__device__ int    g_bsums [1024];

// ---------------- CSR build ----------------

__global__ void k_count(const int* __restrict__ dst, int E) {
    int e = blockIdx.x * blockDim.x + threadIdx.x;
    if (e < E) atomicAdd(&g_deg[dst[e]], 1);
}

// exclusive scan of g_deg -> g_rowptr (warp-shuffle scan); also dinv = rsqrt(deg+1)
__global__ void k_scan1(int N) {
    __shared__ int wsum[32];
    int t = threadIdx.x, i = blockIdx.x * 1024 + t;
    int lane = t & 31, wid = t >> 5;
    int v = (i < N) ? g_deg[i] : 0;
    if (i < N) g_dinv[i] = rsqrtf((float)v + 1.0f);
    int x = v;
#pragma unroll
    for (int off = 1; off < 32; off <<= 1) {
        int y = __shfl_up_sync(0xffffffffu, x, off);
        if (lane >= off) x += y;
    }
    if (lane == 31) wsum[wid] = x;
    __syncthreads();
    if (wid == 0) {
        int w = wsum[lane];
#pragma unroll
        for (int off = 1; off < 32; off <<= 1) {
            int y = __shfl_up_sync(0xffffffffu, w, off);
            if (lane >= off) w += y;
        }
        wsum[lane] = w;
    }
    __syncthreads();
    int boff = (wid > 0) ? wsum[wid - 1] : 0;
    int incl = x + boff;
    if (i < N) g_rowptr[i] = incl - v;          // exclusive
    if (t == 1023) g_bsums[blockIdx.x] = incl;
}

__global__ void k_scan2(int nb) {
    __shared__ int wsum[32];
    int t = threadIdx.x, lane = t & 31, wid = t >> 5;
    int v = (t < nb) ? g_bsums[t] : 0;
    int x = v;
#pragma unroll
    for (int off = 1; off < 32; off <<= 1) {
        int y = __shfl_up_sync(0xffffffffu, x, off);
        if (lane >= off) x += y;
    }
    if (lane == 31) wsum[wid] = x;
    __syncthreads();
    if (wid == 0) {
        int w = wsum[lane];
#pragma unroll
        for (int off = 1; off < 32; off <<= 1) {
            int y = __shfl_up_sync(0xffffffffu, w, off);
            if (lane >= off) w += y;
        }
        wsum[lane] = w;
    }
    __syncthreads();
    int boff = (wid > 0) ? wsum[wid - 1] : 0;
    if (t < nb) g_bsums[t] = x + boff - v;      // exclusive
}

__global__ void k_scan3(int N, int E) {
    int i = blockIdx.x * 1024 + threadIdx.x;
    if (i < N) {
        int rp = g_rowptr[i] + g_bsums[blockIdx.x];
        g_rowptr[i] = rp;
        g_cursor[i] = rp;                       // fill cursors start at row base
    }
    if (i == 0) g_rowptr[N] = E;
}

// fused: CSR fill (idx < E) + node encoder (idx < N*32, 2 cols/thread, half2 out).
// hp16 = half( dinv * relu(x @ Wn + bn) )
__global__ void k_fill_encode(const int* __restrict__ src, const int* __restrict__ dst,
                              const float* __restrict__ x,
                              const float* __restrict__ Wn,
                              const float* __restrict__ bn, int N, int E) {
    int idx = blockIdx.x * blockDim.x + threadIdx.x;
    if (idx < E) {
        int pos = atomicAdd(&g_cursor[dst[idx]], 1);
        g_csr[pos] = src[idx];
    }
    if (idx < N * 32) {
        int n = idx >> 5, c2 = idx & 31;
        int c0 = c2 * 2;
        const float* xr = x + n * 5;
        float a0 = __ldg(&bn[c0]), a1 = __ldg(&bn[c0 + 1]);
#pragma unroll
        for (int j = 0; j < 5; j++) {
            float xv = __ldg(&xr[j]);
            a0 = fmaf(xv, __ldg(&Wn[j * H + c0]),     a0);
            a1 = fmaf(xv, __ldg(&Wn[j * H + c0 + 1]), a1);
        }
        float d = g_dinv[n];
        ((half2*)g_hp16)[idx] =
            __floats2half2_rn(d * fmaxf(a0, 0.f), d * fmaxf(a1, 0.f));
    }
}

// ---------------- feature pipeline ----------------

__device__ __forceinline__ void acc_add(float2 (&a)[4], uint4 v) {
    half2 h0 = *(half2*)&v.x, h1 = *(half2*)&v.y;
    half2 h2 = *(half2*)&v.z, h3 = *(half2*)&v.w;
    float2 f0 = __half22float2(h0), f1 = __half22float2(h1);
    float2 f2 = __half22float2(h2), f3 = __half22float2(h3);
    a[0].x += f0.x; a[0].y += f0.y;
    a[1].x += f1.x; a[1].y += f1.y;
    a[2].x += f2.x; a[2].y += f2.y;
    a[3].x += f3.x; a[3].y += f3.y;
}

// a_n = dinv_n * ( sum_{s in in(n)} h'_s + h'_n ) ; warp per node.
// Quarter-warp per edge: 8 lanes x uint4(=8 halves) cover one 128B fp16 row.
// One SHFL.IDX (per-lane source j+q) + one LDG.128 serve FOUR edges; 2x unroll
// keeps 2 independent LDG.128 in flight (the R6-proven MLP structure).
__global__ void k_gather(int N) {
    int warp = (blockIdx.x * blockDim.x + threadIdx.x) >> 5;
    if (warp >= N) return;
    int lane = threadIdx.x & 31;
    int q  = lane >> 3;            // quarter 0..3
    int l8 = lane & 7;
    int beg = g_rowptr[warp];
    int cnt = g_deg[warp];
    const uint4* hp = (const uint4*)g_hp16;   // row n = hp[n*8 .. n*8+7]
    float2 a[4] = {{0.f,0.f},{0.f,0.f},{0.f,0.f},{0.f,0.f}};
    float2 b[4] = {{0.f,0.f},{0.f,0.f},{0.f,0.f},{0.f,0.f}};
    if (q == 0) acc_add(a, __ldg(&hp[warp * 8 + l8]));   // self term

    for (int b0 = 0; b0 < cnt; b0 += 32) {
        int idx = b0 + lane;
        int sl  = (idx < cnt) ? __ldg(&g_csr[beg + idx]) : 0;
        int m   = min(32, cnt - b0);
        int j   = 0;
        for (; j + 7 < m; j += 8) {            // 8 edges: 2 shfl + 2 LDG.128
            int s0 = __shfl_sync(0xffffffffu, sl, j + q);
            int s1 = __shfl_sync(0xffffffffu, sl, j + 4 + q);
            uint4 v0 = __ldg(&hp[s0 * 8 + l8]);
            uint4 v1 = __ldg(&hp[s1 * 8 + l8]);
            acc_add(a, v0);
            acc_add(b, v1);
        }
        for (; j + 3 < m; j += 4) {            // 4 edges: 1 shfl + 1 LDG.128
            int s0 = __shfl_sync(0xffffffffu, sl, j + q);
            uint4 v0 = __ldg(&hp[s0 * 8 + l8]);
            acc_add(a, v0);
        }
        if (j < m) {                           // tail: 1-3 edges, one masked iter
            int jj = j + q;
            int s0 = __shfl_sync(0xffffffffu, sl, (jj < m) ? jj : 0);
            if (jj < m) acc_add(a, __ldg(&hp[s0 * 8 + l8]));
        }
    }
#pragma unroll
    for (int i = 0; i < 4; i++) { a[i].x += b[i].x; a[i].y += b[i].y; }
    // reduce the 4 quarters (8 floats per lane)
#pragma unroll
    for (int i = 0; i < 4; i++) {
        a[i].x += __shfl_xor_sync(0xffffffffu, a[i].x, 8);
        a[i].y += __shfl_xor_sync(0xffffffffu, a[i].y, 8);
        a[i].x += __shfl_xor_sync(0xffffffffu, a[i].x, 16);
        a[i].y += __shfl_xor_sync(0xffffffffu, a[i].y, 16);
    }
    if (q == 0) {
        float di = g_dinv[warp];
        float4* out4 = (float4*)g_a;
        out4[warp * 16 + l8 * 2] =
            make_float4(di * a[0].x, di * a[0].y, di * a[1].x, di * a[1].y);
        out4[warp * 16 + l8 * 2 + 1] =
            make_float4(di * a[2].x, di * a[2].y, di * a[3].x, di * a[3].y);
    }
}

// hp16 = half( dinv * relu(a @ W + bc) ) ; 64-row tile, 4r x 4c per thread
// W transposed in smem, row stride 68 floats (== 4 mod 32 -> conflict-free LDS.128)
__global__ void k_matmul(const float* __restrict__ W, const float* __restrict__ bc, int N) {
    __shared__ float4 Wt[4][16][17];   // col c = 4*cg + j  ->  Wt[j][cg][k4]
    __shared__ float4 hs[64][16];      // a-tile [row][k4]
    __shared__ float  dv[64];
    __shared__ float  bs[64];
    int tid = threadIdx.x;             // 256 threads
    for (int i = tid; i < H * H; i += 256) {
        int k = i >> 6, c = i & 63;
        ((float*)&Wt[c & 3][c >> 2][0])[k] = W[i];
    }
    int base = blockIdx.x * 64;
    const float4* a4 = (const float4*)g_a;
    for (int i = tid; i < 64 * 16; i += 256) {
        int r = i >> 4, k4 = i & 15;
        int n = base + r;
        hs[r][k4] = (n < N) ? a4[n * 16 + k4] : make_float4(0.f, 0.f, 0.f, 0.f);
    }
    if (tid < 64) {
        bs[tid] = bc[tid];
        int n = base + tid;
        dv[tid] = (n < N) ? g_dinv[n] : 0.f;
    }
    __syncthreads();

    int cg = tid & 15, rg = tid >> 4;
    float4 acc[4];
#pragma unroll
    for (int m = 0; m < 4; m++) acc[m] = make_float4(0.f, 0.f, 0.f, 0.f);

#pragma unroll
    for (int k4 = 0; k4 < 16; k4++) {
        float4 w0 = Wt[0][cg][k4];
        float4 w1 = Wt[1][cg][k4];
        float4 w2 = Wt[2][cg][k4];
        float4 w3 = Wt[3][cg][k4];
#pragma unroll
        for (int m = 0; m < 4; m++) {
            float4 h = hs[rg + 16 * m][k4];
            acc[m].x = fmaf(h.x, w0.x, fmaf(h.y, w0.y, fmaf(h.z, w0.z, fmaf(h.w, w0.w, acc[m].x))));
            acc[m].y = fmaf(h.x, w1.x, fmaf(h.y, w1.y, fmaf(h.z, w1.z, fmaf(h.w, w1.w, acc[m].y))));
            acc[m].z = fmaf(h.x, w2.x, fmaf(h.y, w2.y, fmaf(h.z, w2.z, fmaf(h.w, w2.w, acc[m].z))));
            acc[m].w = fmaf(h.x, w3.x, fmaf(h.y, w3.y, fmaf(h.z, w3.z, fmaf(h.w, w3.w, acc[m].w))));
        }
    }

#pragma unroll
    for (int m = 0; m < 4; m++) {
        int r = rg + 16 * m;
        int n = base + r;
        if (n < N) {
            float d = dv[r];
            half2 p0 = __floats2half2_rn(d * fmaxf(acc[m].x + bs[4 * cg + 0], 0.f),
                                         d * fmaxf(acc[m].y + bs[4 * cg + 1], 0.f));
            half2 p1 = __floats2half2_rn(d * fmaxf(acc[m].z + bs[4 * cg + 2], 0.f),
                                         d * fmaxf(acc[m].w + bs[4 * cg + 3], 0.f));
            uint2 u;
            u.x = *(unsigned*)&p0;
            u.y = *(unsigned*)&p1;
            ((uint2*)g_hp16)[n * 16 + cg] = u;   // row = 16 uint2 = 128B
        }
    }
}

// Fused last conv layer + both heads (reads g_a fp32).
__global__ void k_conv_heads(const float* __restrict__ Wc, const float* __restrict__ bc,
                             const float* __restrict__ Wd1, const float* __restrict__ bd1,
                             const float* __restrict__ Wd2, const float* __restrict__ bd2,
                             const float* __restrict__ Wi1, const float* __restrict__ bi1,
                             const float* __restrict__ Wi2, const float* __restrict__ bi2,
                             float* __restrict__ out, int N) {
    __shared__ float4 WtC[4][16][17];
    __shared__ float4 WtH[4][16][17];
    __shared__ float4 hs[64][16];
    __shared__ float  bs[64], b1s[64], w2s[64], b2s[2];
    int tid = threadIdx.x;             // 256 threads
    for (int i = tid; i < H * H; i += 256) {
        int k = i >> 6, c = i & 63;
        ((float*)&WtC[c & 3][c >> 2][0])[k] = Wc[i];
        float wh = (c < 32) ? Wd1[k * 32 + c] : Wi1[k * 32 + (c - 32)];
        ((float*)&WtH[c & 3][c >> 2][0])[k] = wh;
    }
    if (tid < 64) {
        bs[tid]  = bc[tid];
        b1s[tid] = (tid < 32) ? bd1[tid] : bi1[tid - 32];
        w2s[tid] = (tid < 32) ? Wd2[tid] : Wi2[tid - 32];
    }
    if (tid == 0) { b2s[0] = bd2[0]; b2s[1] = bi2[0]; }
    int base = blockIdx.x * 64;
    const float4* a4 = (const float4*)g_a;
    for (int i = tid; i < 64 * 16; i += 256) {
        int r = i >> 4, k4 = i & 15;
        int n = base + r;
        hs[r][k4] = (n < N) ? a4[n * 16 + k4] : make_float4(0.f, 0.f, 0.f, 0.f);
    }
    __syncthreads();

    int cg = tid & 15, rg = tid >> 4;
    float4 acc[4];
#pragma unroll
    for (int m = 0; m < 4; m++) acc[m] = make_float4(0.f, 0.f, 0.f, 0.f);

    // ---- stage 1: conv matmul ----
#pragma unroll
    for (int k4 = 0; k4 < 16; k4++) {
        float4 w0 = WtC[0][cg][k4];
        float4 w1 = WtC[1][cg][k4];
        float4 w2 = WtC[2][cg][k4];
        float4 w3 = WtC[3][cg][k4];
#pragma unroll
        for (int m = 0; m < 4; m++) {
            float4 h = hs[rg + 16 * m][k4];
            acc[m].x = fmaf(h.x, w0.x, fmaf(h.y, w0.y, fmaf(h.z, w0.z, fmaf(h.w, w0.w, acc[m].x))));
            acc[m].y = fmaf(h.x, w1.x, fmaf(h.y, w1.y, fmaf(h.z, w1.z, fmaf(h.w, w1.w, acc[m].y))));
            acc[m].z = fmaf(h.x, w2.x, fmaf(h.y, w2.y, fmaf(h.z, w2.z, fmaf(h.w, w2.w, acc[m].z))));
            acc[m].w = fmaf(h.x, w3.x, fmaf(h.y, w3.y, fmaf(h.z, w3.z, fmaf(h.w, w3.w, acc[m].w))));
        }
    }
    __syncthreads();                   // all hs reads done before overwrite

#pragma unroll
    for (int m = 0; m < 4; m++) {
        float4 o;
        o.x = fmaxf(acc[m].x + bs[4 * cg + 0], 0.f);
        o.y = fmaxf(acc[m].y + bs[4 * cg + 1], 0.f);
        o.z = fmaxf(acc[m].z + bs[4 * cg + 2], 0.f);
        o.w = fmaxf(acc[m].w + bs[4 * cg + 3], 0.f);
        hs[rg + 16 * m][cg] = o;
        acc[m] = make_float4(0.f, 0.f, 0.f, 0.f);
    }
    __syncthreads();

    // ---- stage 2: head layer-1 matmul ----
#pragma unroll
    for (int k4 = 0; k4 < 16; k4++) {
        float4 w0 = WtH[0][cg][k4];
        float4 w1 = WtH[1][cg][k4];
        float4 w2 = WtH[2][cg][k4];
        float4 w3 = WtH[3][cg][k4];
#pragma unroll
        for (int m = 0; m < 4; m++) {
            float4 h = hs[rg + 16 * m][k4];
            acc[m].x = fmaf(h.x, w0.x, fmaf(h.y, w0.y, fmaf(h.z, w0.z, fmaf(h.w, w0.w, acc[m].x))));
            acc[m].y = fmaf(h.x, w1.x, fmaf(h.y, w1.y, fmaf(h.z, w1.z, fmaf(h.w, w1.w, acc[m].y))));
            acc[m].z = fmaf(h.x, w2.x, fmaf(h.y, w2.y, fmaf(h.z, w2.z, fmaf(h.w, w2.w, acc[m].z))));
            acc[m].w = fmaf(h.x, w3.x, fmaf(h.y, w3.y, fmaf(h.z, w3.z, fmaf(h.w, w3.w, acc[m].w))));
        }
    }

    // ---- stage 3: relu(t+b1) . w2, half-warp reduce (16 threads per row) ----
    float w2a = w2s[4 * cg + 0], w2b = w2s[4 * cg + 1];
    float w2c = w2s[4 * cg + 2], w2d = w2s[4 * cg + 3];
    float b1a = b1s[4 * cg + 0], b1b = b1s[4 * cg + 1];
    float b1c = b1s[4 * cg + 2], b1d = b1s[4 * cg + 3];
#pragma unroll
    for (int m = 0; m < 4; m++) {
        int r = rg + 16 * m;
        int n = base + r;
        float local = fmaxf(acc[m].x + b1a, 0.f) * w2a
                    + fmaxf(acc[m].y + b1b, 0.f) * w2b
                    + fmaxf(acc[m].z + b1c, 0.f) * w2c
                    + fmaxf(acc[m].w + b1d, 0.f) * w2d;
        local += __shfl_xor_sync(0xffffffffu, local, 1);
        local += __shfl_xor_sync(0xffffffffu, local, 2);
        local += __shfl_xor_sync(0xffffffffu, local, 4);
        if (n < N) {
            if (cg == 0) out[n]     = local + b2s[0];   // demand    (cols 0-31)
            if (cg == 8) out[N + n] = local + b2s[1];   // inventory (cols 32-63)
        }
    }
}

// ---------------- launch ----------------
extern "C" void kernel_launch(void* const* d_in, const int* in_sizes, int n_in,
                              void* d_out, int out_size) {
    const float* x   = (const float*)d_in[0];
    const int*   ei  = (const int*)  d_in[1];
    const float* Wn  = (const float*)d_in[3];
    const float* bn  = (const float*)d_in[4];
    const float* Wc  = (const float*)d_in[7];
    const float* bc  = (const float*)d_in[8];
    const float* Wd1 = (const float*)d_in[9];
    const float* bd1 = (const float*)d_in[10];
    const float* Wd2 = (const float*)d_in[11];
    const float* bd2 = (const float*)d_in[12];
    const float* Wi1 = (const float*)d_in[13];
    const float* bi1 = (const float*)d_in[14];
    const float* Wi2 = (const float*)d_in[15];
    const float* bi2 = (const float*)d_in[16];
    float* out = (float*)d_out;

    int N = in_sizes[0] / 5;
    int E = in_sizes[1] / 2;
    const int* src = ei;       // edge_index[0]
    const int* dst = ei + E;   // edge_index[1]

    void* degPtr = nullptr;
    cudaGetSymbolAddress(&degPtr, g_deg);
    cudaMemsetAsync(degPtr, 0, (size_t)N * sizeof(int));

    int nb = (N + 1023) / 1024;
    k_count<<<(E + 255) / 256, 256>>>(dst, E);
    k_scan1<<<nb, 1024>>>(N);
    k_scan2<<<1, 1024>>>(nb);
    k_scan3<<<nb, 1024>>>(N, E);
    int feWork = (N * 32 > E) ? N * 32 : E;
    k_fill_encode<<<(feWork + 255) / 256, 256>>>(src, dst, x, Wn, bn, N, E);

    int gatherBlocks = (N * 32 + 255) / 256;
    int mmBlocks     = (N + 63) / 64;

    k_gather<<<gatherBlocks, 256>>>(N);
    k_matmul<<<mmBlocks, 256>>>(Wc + 0 * H * H, bc + 0 * H, N);
    k_gather<<<gatherBlocks, 256>>>(N);
    k_matmul<<<mmBlocks, 256>>>(Wc + 1 * H * H, bc + 1 * H, N);
    k_gather<<<gatherBlocks, 256>>>(N);
    k_conv_heads<<<mmBlocks, 256>>>(Wc + 2 * H * H, bc + 2 * H,
                                    Wd1, bd1, Wd2, bd2, Wi1, bi1, Wi2, bi2, out, N);
}